// round 1
// baseline (speedup 1.0000x reference)
#include <cuda_runtime.h>
#include <cstdint>
#include <cstddef>

#define N_NODES 8192
#define DIN     512
#define DOUT    256
#define ALPHA   0.2f
#define NEG_INF -9e15f

// ---------------- scratch (device globals; no allocations allowed) ----------
__device__ float g_Wh[(size_t)N_NODES * DOUT];   // 8 MB
__device__ float g_src[N_NODES];
__device__ float g_dst[N_NODES];
__device__ float g_rmax[N_NODES];
__device__ float g_rsum[N_NODES];

// ---------------- helpers ----------------------------------------------------
__device__ __forceinline__ uint32_t f2tf32(float x) {
    uint32_t r;
    asm("cvt.rna.tf32.f32 %0, %1;" : "=r"(r) : "f"(x));
    return r;
}

__device__ __forceinline__ void mma_tf32(float* c,
                                         uint32_t a0, uint32_t a1, uint32_t a2, uint32_t a3,
                                         uint32_t b0, uint32_t b1) {
    asm volatile(
        "mma.sync.aligned.m16n8k8.row.col.f32.tf32.tf32.f32 "
        "{%0,%1,%2,%3}, {%4,%5,%6,%7}, {%8,%9}, {%0,%1,%2,%3};\n"
        : "+f"(c[0]), "+f"(c[1]), "+f"(c[2]), "+f"(c[3])
        : "r"(a0), "r"(a1), "r"(a2), "r"(a3), "r"(b0), "r"(b1));
}

// ---------------- K1: Wh = X @ W  (fp32, tiled) ------------------------------
// grid (128, 4), block 256. BM=64, BN=64, BK=16, 4x4 microtile.
__global__ void __launch_bounds__(256) k1_gemm(const float* __restrict__ X,
                                               const float* __restrict__ W) {
    __shared__ float As[16][68];   // stored transposed [k][m]
    __shared__ float Bs[16][68];   // [k][n]
    int t  = threadIdx.x;
    int tx = t & 15, ty = t >> 4;
    int m0 = blockIdx.x * 64, n0 = blockIdx.y * 64;

    float acc[4][4];
    #pragma unroll
    for (int i = 0; i < 4; i++)
        #pragma unroll
        for (int j = 0; j < 4; j++) acc[i][j] = 0.f;

    for (int k0 = 0; k0 < DIN; k0 += 16) {
        {   // A tile: 64 rows x 16 cols
            int row = t >> 2, c4 = (t & 3) * 4;
            float4 v = *(const float4*)&X[(size_t)(m0 + row) * DIN + k0 + c4];
            As[c4 + 0][row] = v.x; As[c4 + 1][row] = v.y;
            As[c4 + 2][row] = v.z; As[c4 + 3][row] = v.w;
        }
        {   // B tile: 16 rows x 64 cols
            int row = t >> 4, c4 = (t & 15) * 4;
            *(float4*)&Bs[row][c4] = *(const float4*)&W[(size_t)(k0 + row) * DOUT + n0 + c4];
        }
        __syncthreads();
        #pragma unroll
        for (int k = 0; k < 16; k++) {
            float4 a4 = *(float4*)&As[k][ty * 4];
            float4 b4 = *(float4*)&Bs[k][tx * 4];
            float av[4] = {a4.x, a4.y, a4.z, a4.w};
            float bv[4] = {b4.x, b4.y, b4.z, b4.w};
            #pragma unroll
            for (int i = 0; i < 4; i++)
                #pragma unroll
                for (int j = 0; j < 4; j++) acc[i][j] += av[i] * bv[j];
        }
        __syncthreads();
    }
    #pragma unroll
    for (int i = 0; i < 4; i++)
        #pragma unroll
        for (int j = 0; j < 4; j++)
            g_Wh[(size_t)(m0 + ty * 4 + i) * DOUT + n0 + tx * 4 + j] = acc[i][j];
}

// ---------------- K2: src/dst projections (warp per row) ---------------------
// grid 1024, block 256 (8 warps)
__global__ void __launch_bounds__(256) k2_srcdst(const float* __restrict__ a) {
    int lane = threadIdx.x & 31, w = threadIdx.x >> 5;
    int i = blockIdx.x * 8 + w;
    float s1 = 0.f, s2 = 0.f;
    #pragma unroll
    for (int c = lane; c < DOUT; c += 32) {
        float wh = g_Wh[(size_t)i * DOUT + c];
        s1 += wh * a[c];
        s2 += wh * a[DOUT + c];
    }
    #pragma unroll
    for (int o = 16; o > 0; o >>= 1) {
        s1 += __shfl_xor_sync(0xffffffffu, s1, o);
        s2 += __shfl_xor_sync(0xffffffffu, s2, o);
    }
    if (lane == 0) { g_src[i] = s1; g_dst[i] = s2; }
}

// ---------------- K3: per-row max and sum(exp(e - m)) ------------------------
// grid 8192 (one CTA per row), block 256. adj row read once; e kept in regs.
__global__ void __launch_bounds__(256) k3_rowstats(const int* __restrict__ adj) {
    int i = blockIdx.x;
    int t = threadIdx.x;
    int lane = t & 31, w = t >> 5;
    __shared__ float red[8];
    __shared__ float bcast;

    float si = g_src[i];
    float ev[32];
    float mx = NEG_INF;
    #pragma unroll
    for (int s = 0; s < 8; s++) {
        int j = (s * 256 + t) * 4;
        int4   a4 = *(const int4*)&adj[(size_t)i * N_NODES + j];
        float4 d4 = *(const float4*)&g_dst[j];
        float xs[4] = {si + d4.x, si + d4.y, si + d4.z, si + d4.w};
        int   am[4] = {a4.x, a4.y, a4.z, a4.w};
        #pragma unroll
        for (int c = 0; c < 4; c++) {
            float x = xs[c];
            float e = x > 0.f ? x : ALPHA * x;
            e = (am[c] > 0) ? e : NEG_INF;
            ev[s * 4 + c] = e;
            mx = fmaxf(mx, e);
        }
    }
    #pragma unroll
    for (int o = 16; o > 0; o >>= 1) mx = fmaxf(mx, __shfl_xor_sync(0xffffffffu, mx, o));
    if (lane == 0) red[w] = mx;
    __syncthreads();
    if (t == 0) {
        float m2 = red[0];
        #pragma unroll
        for (int q = 1; q < 8; q++) m2 = fmaxf(m2, red[q]);
        bcast = m2;
    }
    __syncthreads();
    float bm = bcast;

    float sum = 0.f;
    #pragma unroll
    for (int q = 0; q < 32; q++) sum += __expf(ev[q] - bm);
    #pragma unroll
    for (int o = 16; o > 0; o >>= 1) sum += __shfl_xor_sync(0xffffffffu, sum, o);
    __syncthreads();              // protect red[] reuse
    if (lane == 0) red[w] = sum;
    __syncthreads();
    if (t == 0) {
        float s2 = 0.f;
        #pragma unroll
        for (int q = 0; q < 8; q++) s2 += red[q];
        g_rmax[i] = bm;
        g_rsum[i] = s2;
    }
}

// ---------------- K4: h' = softmax(P) @ Wh, fused, tf32 MMA ------------------
// grid 128 (64-row tiles), block 256 (8 warps: 2 in M x 4 in N).
// Per k-tile of 32: build P (tf32) in smem from adj/src/dst/m, stage Wh (tf32),
// run m16n8k8 tf32 MMAs. Epilogue: /rowsum, ELU.
__global__ void __launch_bounds__(256) k4_attn(const int* __restrict__ adj,
                                               float* __restrict__ out) {
    __shared__ uint32_t Ps[64][36];     // P tile, tf32 bits, pad 36 (bank-clean)
    __shared__ uint32_t Whs[32][260];   // Wh tile, tf32 bits, pad 260
    __shared__ float src_s[64], m_s[64], linv_s[64];

    int t    = threadIdx.x;
    int lane = t & 31, w = t >> 5;
    int wm = w & 1;        // 0..1  -> 32-row half
    int wn = w >> 1;       // 0..3  -> 64-col quarter
    int I0 = blockIdx.x * 64;

    if (t < 64) {
        src_s[t]  = g_src[I0 + t];
        m_s[t]    = g_rmax[I0 + t];
        linv_s[t] = 1.0f / g_rsum[I0 + t];
    }

    float acc[2][8][4];
    #pragma unroll
    for (int ma = 0; ma < 2; ma++)
        #pragma unroll
        for (int na = 0; na < 8; na++)
            #pragma unroll
            for (int q = 0; q < 4; q++) acc[ma][na][q] = 0.f;

    __syncthreads();

    for (int k0 = 0; k0 < N_NODES; k0 += 32) {
        // ---- P tile: 64 rows x 32 cols, on the fly ----
        #pragma unroll
        for (int s = 0; s < 2; s++) {
            int r  = s * 32 + (t >> 3);
            int kc = (t & 7) * 4;
            int i  = I0 + r;
            int4   a4 = *(const int4*)&adj[(size_t)i * N_NODES + k0 + kc];
            float4 dv = *(const float4*)&g_dst[k0 + kc];
            float si = src_s[r], mi = m_s[r];
            float xs[4] = {si + dv.x, si + dv.y, si + dv.z, si + dv.w};
            int   am[4] = {a4.x, a4.y, a4.z, a4.w};
            #pragma unroll
            for (int c = 0; c < 4; c++) {
                float x = xs[c];
                float e = x > 0.f ? x : ALPHA * x;
                e = (am[c] > 0) ? e : NEG_INF;
                float p = __expf(e - mi);
                Ps[r][kc + c] = f2tf32(p);
            }
        }
        // ---- Wh tile: 32 rows x 256 cols ----
        #pragma unroll
        for (int q = 0; q < 8; q++) {
            int f   = q * 256 + t;         // float4 index
            int row = f >> 6, c4 = (f & 63) * 4;
            float4 v = *(const float4*)&g_Wh[(size_t)(k0 + row) * DOUT + c4];
            uint4 u = make_uint4(f2tf32(v.x), f2tf32(v.y), f2tf32(v.z), f2tf32(v.w));
            *(uint4*)&Whs[row][c4] = u;
        }
        __syncthreads();

        // ---- MMAs: 4 k-atoms of K=8 ----
        #pragma unroll
        for (int kk = 0; kk < 4; kk++) {
            uint32_t b[8][2];
            int kr = kk * 8 + (lane & 3);
            int cb = wn * 64 + (lane >> 2);
            #pragma unroll
            for (int na = 0; na < 8; na++) {
                b[na][0] = Whs[kr][cb + na * 8];
                b[na][1] = Whs[kr + 4][cb + na * 8];
            }
            #pragma unroll
            for (int ma = 0; ma < 2; ma++) {
                int ar = wm * 32 + ma * 16 + (lane >> 2);
                int ac = kk * 8 + (lane & 3);
                uint32_t a0 = Ps[ar][ac];
                uint32_t a1 = Ps[ar + 8][ac];
                uint32_t a2 = Ps[ar][ac + 4];
                uint32_t a3 = Ps[ar + 8][ac + 4];
                #pragma unroll
                for (int na = 0; na < 8; na++)
                    mma_tf32(acc[ma][na], a0, a1, a2, a3, b[na][0], b[na][1]);
            }
        }
        __syncthreads();
    }

    // ---- epilogue: normalize by rowsum, ELU, store ----
    #pragma unroll
    for (int ma = 0; ma < 2; ma++) {
        int r0 = wm * 32 + ma * 16 + (lane >> 2);
        #pragma unroll
        for (int na = 0; na < 8; na++) {
            int c0 = wn * 64 + na * 8 + (lane & 3) * 2;
            #pragma unroll
            for (int q = 0; q < 4; q++) {
                int r = r0 + ((q >= 2) ? 8 : 0);
                int c = c0 + (q & 1);
                float v = acc[ma][na][q] * linv_s[r];
                v = (v > 0.f) ? v : expm1f(v);
                out[(size_t)(I0 + r) * DOUT + c] = v;
            }
        }
    }
}

// ---------------- launch ------------------------------------------------------
extern "C" void kernel_launch(void* const* d_in, const int* in_sizes, int n_in,
                              void* d_out, int out_size) {
    const float* X   = (const float*)d_in[0];   // features [8192,512]
    const int*   adj = (const int*)  d_in[1];   // adj      [8192,8192]
    const float* W   = (const float*)d_in[2];   // W        [512,256]
    const float* a   = (const float*)d_in[3];   // a        [512,1]
    float* out = (float*)d_out;                 // [8192,256]

    k1_gemm   <<<dim3(N_NODES / 64, DOUT / 64), 256>>>(X, W);
    k2_srcdst <<<N_NODES / 8, 256>>>(a);
    k3_rowstats<<<N_NODES, 256>>>(adj);
    k4_attn   <<<N_NODES / 64, 256>>>(adj, out);
}

// round 3
// speedup vs baseline: 2.0914x; 2.0914x over previous
#include <cuda_runtime.h>
#include <cstdint>
#include <cstddef>

#define N_NODES 8192
#define DIN     512
#define DOUT    256
#define ALPHA   0.2f
#define NEG_INF -9e15f

// ---------------- scratch (device globals; no allocations allowed) ----------
__device__ float    g_Wh  [(size_t)N_NODES * DOUT];   // 8 MB fp32 (for k2)
__device__ uint32_t g_Whtf[(size_t)N_NODES * DOUT];   // 8 MB tf32 bits (for k4)
__device__ float g_src[N_NODES];
__device__ float g_dst[N_NODES];
__device__ float g_rmax[N_NODES];
__device__ float g_rsum[N_NODES];

// ---------------- helpers ----------------------------------------------------
__device__ __forceinline__ uint32_t f2tf32(float x) {
    uint32_t r;
    asm("cvt.rna.tf32.f32 %0, %1;" : "=r"(r) : "f"(x));
    return r;
}

__device__ __forceinline__ void mma_tf32(float* c,
                                         uint32_t a0, uint32_t a1, uint32_t a2, uint32_t a3,
                                         uint32_t b0, uint32_t b1) {
    asm volatile(
        "mma.sync.aligned.m16n8k8.row.col.f32.tf32.tf32.f32 "
        "{%0,%1,%2,%3}, {%4,%5,%6,%7}, {%8,%9}, {%0,%1,%2,%3};\n"
        : "+f"(c[0]), "+f"(c[1]), "+f"(c[2]), "+f"(c[3])
        : "r"(a0), "r"(a1), "r"(a2), "r"(a3), "r"(b0), "r"(b1));
}

__device__ __forceinline__ void cp_async16(uint32_t smem_addr, const void* gptr) {
    asm volatile("cp.async.cg.shared.global [%0], [%1], 16;\n"
                 :: "r"(smem_addr), "l"(gptr));
}
__device__ __forceinline__ void cp_commit() {
    asm volatile("cp.async.commit_group;\n" ::: "memory");
}
template <int N>
__device__ __forceinline__ void cp_wait() {
    asm volatile("cp.async.wait_group %0;\n" :: "n"(N) : "memory");
}

// ---------------- K1: Wh = X @ W  (fp32, tiled) ------------------------------
__global__ void __launch_bounds__(256) k1_gemm(const float* __restrict__ X,
                                               const float* __restrict__ W) {
    __shared__ float As[16][68];   // [k][m]
    __shared__ float Bs[16][68];   // [k][n]
    int t  = threadIdx.x;
    int tx = t & 15, ty = t >> 4;
    int m0 = blockIdx.x * 64, n0 = blockIdx.y * 64;

    float acc[4][4];
    #pragma unroll
    for (int i = 0; i < 4; i++)
        #pragma unroll
        for (int j = 0; j < 4; j++) acc[i][j] = 0.f;

    for (int k0 = 0; k0 < DIN; k0 += 16) {
        {
            int row = t >> 2, c4 = (t & 3) * 4;
            float4 v = *(const float4*)&X[(size_t)(m0 + row) * DIN + k0 + c4];
            As[c4 + 0][row] = v.x; As[c4 + 1][row] = v.y;
            As[c4 + 2][row] = v.z; As[c4 + 3][row] = v.w;
        }
        {
            int row = t >> 4, c4 = (t & 15) * 4;
            *(float4*)&Bs[row][c4] = *(const float4*)&W[(size_t)(k0 + row) * DOUT + n0 + c4];
        }
        __syncthreads();
        #pragma unroll
        for (int k = 0; k < 16; k++) {
            float4 a4 = *(float4*)&As[k][ty * 4];
            float4 b4 = *(float4*)&Bs[k][tx * 4];
            float av[4] = {a4.x, a4.y, a4.z, a4.w};
            float bv[4] = {b4.x, b4.y, b4.z, b4.w};
            #pragma unroll
            for (int i = 0; i < 4; i++)
                #pragma unroll
                for (int j = 0; j < 4; j++) acc[i][j] += av[i] * bv[j];
        }
        __syncthreads();
    }
    #pragma unroll
    for (int i = 0; i < 4; i++)
        #pragma unroll
        for (int j = 0; j < 4; j++) {
            size_t idx = (size_t)(m0 + ty * 4 + i) * DOUT + n0 + tx * 4 + j;
            g_Wh[idx]   = acc[i][j];
            g_Whtf[idx] = f2tf32(acc[i][j]);
        }
}

// ---------------- K2: src/dst projections (warp per row) ---------------------
__global__ void __launch_bounds__(256) k2_srcdst(const float* __restrict__ a) {
    int lane = threadIdx.x & 31, w = threadIdx.x >> 5;
    int i = blockIdx.x * 8 + w;
    float s1 = 0.f, s2 = 0.f;
    #pragma unroll
    for (int c = lane; c < DOUT; c += 32) {
        float wh = g_Wh[(size_t)i * DOUT + c];
        s1 += wh * a[c];
        s2 += wh * a[DOUT + c];
    }
    #pragma unroll
    for (int o = 16; o > 0; o >>= 1) {
        s1 += __shfl_xor_sync(0xffffffffu, s1, o);
        s2 += __shfl_xor_sync(0xffffffffu, s2, o);
    }
    if (lane == 0) { g_src[i] = s1; g_dst[i] = s2; }
}

// ---------------- K3: per-row max and sum(exp(e - m)) ------------------------
__global__ void __launch_bounds__(256) k3_rowstats(const int* __restrict__ adj) {
    int i = blockIdx.x;
    int t = threadIdx.x;
    int lane = t & 31, w = t >> 5;
    __shared__ float red[8];
    __shared__ float bcast;

    float si = g_src[i];
    float ev[32];
    float mx = NEG_INF;
    #pragma unroll
    for (int s = 0; s < 8; s++) {
        int j = (s * 256 + t) * 4;
        int4   a4 = *(const int4*)&adj[(size_t)i * N_NODES + j];
        float4 d4 = *(const float4*)&g_dst[j];
        float xs[4] = {si + d4.x, si + d4.y, si + d4.z, si + d4.w};
        int   am[4] = {a4.x, a4.y, a4.z, a4.w};
        #pragma unroll
        for (int c = 0; c < 4; c++) {
            float x = xs[c];
            float e = x > 0.f ? x : ALPHA * x;
            e = (am[c] > 0) ? e : NEG_INF;
            ev[s * 4 + c] = e;
            mx = fmaxf(mx, e);
        }
    }
    #pragma unroll
    for (int o = 16; o > 0; o >>= 1) mx = fmaxf(mx, __shfl_xor_sync(0xffffffffu, mx, o));
    if (lane == 0) red[w] = mx;
    __syncthreads();
    if (t == 0) {
        float m2 = red[0];
        #pragma unroll
        for (int q = 1; q < 8; q++) m2 = fmaxf(m2, red[q]);
        bcast = m2;
    }
    __syncthreads();
    float bm = bcast;

    float sum = 0.f;
    #pragma unroll
    for (int q = 0; q < 32; q++) sum += __expf(ev[q] - bm);
    #pragma unroll
    for (int o = 16; o > 0; o >>= 1) sum += __shfl_xor_sync(0xffffffffu, sum, o);
    __syncthreads();
    if (lane == 0) red[w] = sum;
    __syncthreads();
    if (t == 0) {
        float s2 = 0.f;
        #pragma unroll
        for (int q = 0; q < 8; q++) s2 += red[q];
        g_rmax[i] = bm;
        g_rsum[i] = s2;
    }
}

// ---------------- K4: h' = softmax(P) @ Wh, fused, pipelined tf32 MMA --------
// grid (128, 2): x = 64-row tile, y = 128-col half. block 256 (8 warps).
// Canonical one-barrier pipeline: all next-stage writes (cp.async Wh, P build)
// happen AFTER the loop-top cp_wait+barrier, so no buffer is written while
// another warp may still be reading it.
#define WHS_STRIDE 136              // B-frag loads conflict-free
#define PS_STRIDE  36               // A-frag loads conflict-free
#define WHS_STAGE  (32 * WHS_STRIDE)
#define PS_STAGE   (64 * PS_STRIDE)
#define SMEM_U32   (2 * WHS_STAGE + 2 * PS_STAGE + 3 * 64)
#define SMEM_BYTES (SMEM_U32 * 4)
#define NIT        (N_NODES / 32)

__global__ void __launch_bounds__(256, 2) k4_attn(const int* __restrict__ adj,
                                                  float* __restrict__ out) {
    extern __shared__ uint32_t smem[];
    uint32_t* whs    = smem;                         // [2][32][136]
    uint32_t* ps     = smem + 2 * WHS_STAGE;         // [2][64][36]
    float*    src_s  = (float*)(smem + 2 * WHS_STAGE + 2 * PS_STAGE);
    float*    m_s    = src_s + 64;
    float*    linv_s = src_s + 128;

    int t    = threadIdx.x;
    int lane = t & 31, w = t >> 5;
    int wm = w & 1;        // 32-row half
    int wn = w >> 1;       // 32-col quarter of the 128-col half
    int I0 = blockIdx.x * 64;
    int J0 = blockIdx.y * 128;

    if (t < 64) {
        src_s[t]  = g_src[I0 + t];
        m_s[t]    = g_rmax[I0 + t];
        linv_s[t] = 1.0f / g_rsum[I0 + t];
    }

    float acc[2][4][4];
    #pragma unroll
    for (int ma = 0; ma < 2; ma++)
        #pragma unroll
        for (int na = 0; na < 4; na++)
            #pragma unroll
            for (int q = 0; q < 4; q++) acc[ma][na][q] = 0.f;

    // P-build thread mapping: rows r0 = t>>3 and r0+32, cols kc..kc+3
    int r0 = t >> 3;
    int kc = (t & 7) * 4;

    // ---- prologue ----
    int4   adjr[2];
    float4 dvr;
    // tile 0 adj/dst into regs
    adjr[0] = *(const int4*)&adj[(size_t)(I0 + r0)      * N_NODES + kc];
    adjr[1] = *(const int4*)&adj[(size_t)(I0 + r0 + 32) * N_NODES + kc];
    dvr     = *(const float4*)&g_dst[kc];

    // issue Wh stage 0 cp.async (32 rows x 128 cols; 4 x 16B per thread)
    #pragma unroll
    for (int q = 0; q < 4; q++) {
        int id  = q * 256 + t;
        int row = id >> 5, c4 = (id & 31) * 4;
        uint32_t saddr = (uint32_t)__cvta_generic_to_shared(&whs[row * WHS_STRIDE + c4]);
        cp_async16(saddr, &g_Whtf[(size_t)row * DOUT + J0 + c4]);
    }
    cp_commit();

    __syncthreads();   // src_s/m_s visible before first P build

    // build P stage 0
    {
        uint32_t* Pc = ps;
        #pragma unroll
        for (int s = 0; s < 2; s++) {
            int r  = r0 + s * 32;
            float si = src_s[r], mi = m_s[r];
            float xs[4] = {si + dvr.x, si + dvr.y, si + dvr.z, si + dvr.w};
            int   am[4] = {adjr[s].x, adjr[s].y, adjr[s].z, adjr[s].w};
            uint4 pv;
            uint32_t pr[4];
            #pragma unroll
            for (int c = 0; c < 4; c++) {
                float x = xs[c];
                float e = x > 0.f ? x : ALPHA * x;
                e = (am[c] > 0) ? e : NEG_INF;
                pr[c] = f2tf32(__expf(e - mi));
            }
            pv.x = pr[0]; pv.y = pr[1]; pv.z = pr[2]; pv.w = pr[3];
            *(uint4*)&Pc[r * PS_STRIDE + kc] = pv;
        }
    }

    // prefetch adj/dst regs for tile 1
    adjr[0] = *(const int4*)&adj[(size_t)(I0 + r0)      * N_NODES + 32 + kc];
    adjr[1] = *(const int4*)&adj[(size_t)(I0 + r0 + 32) * N_NODES + 32 + kc];
    dvr     = *(const float4*)&g_dst[32 + kc];

    for (int it = 0; it < NIT; ++it) {
        int cur  = it & 1;
        int nxt  = cur ^ 1;
        bool more = (it + 1 < NIT);

        // stage cur fully arrived; all reads of the nxt buffers (MMA of it-1)
        // retired by this barrier -> safe to overwrite nxt below.
        cp_wait<0>();
        __syncthreads();

        if (more) {
            int kn = (it + 1) * 32;
            // issue cp.async for Wh[nxt]
            #pragma unroll
            for (int q = 0; q < 4; q++) {
                int id  = q * 256 + t;
                int row = id >> 5, c4 = (id & 31) * 4;
                uint32_t saddr = (uint32_t)__cvta_generic_to_shared(
                    &whs[nxt * WHS_STAGE + row * WHS_STRIDE + c4]);
                cp_async16(saddr, &g_Whtf[(size_t)(kn + row) * DOUT + J0 + c4]);
            }
            cp_commit();

            // build P[nxt] from prefetched regs (tile it+1)
            uint32_t* Pc = ps + nxt * PS_STAGE;
            #pragma unroll
            for (int s = 0; s < 2; s++) {
                int r  = r0 + s * 32;
                float si = src_s[r], mi = m_s[r];
                float xs[4] = {si + dvr.x, si + dvr.y, si + dvr.z, si + dvr.w};
                int   am[4] = {adjr[s].x, adjr[s].y, adjr[s].z, adjr[s].w};
                uint4 pv;
                uint32_t pr[4];
                #pragma unroll
                for (int c = 0; c < 4; c++) {
                    float x = xs[c];
                    float e = x > 0.f ? x : ALPHA * x;
                    e = (am[c] > 0) ? e : NEG_INF;
                    pr[c] = f2tf32(__expf(e - mi));
                }
                pv.x = pr[0]; pv.y = pr[1]; pv.z = pr[2]; pv.w = pr[3];
                *(uint4*)&Pc[r * PS_STRIDE + kc] = pv;
            }

            // prefetch adj/dst regs for tile it+2 (latency hidden by MMA)
            if (it + 2 < NIT) {
                int kn2 = (it + 2) * 32;
                adjr[0] = *(const int4*)&adj[(size_t)(I0 + r0)      * N_NODES + kn2 + kc];
                adjr[1] = *(const int4*)&adj[(size_t)(I0 + r0 + 32) * N_NODES + kn2 + kc];
                dvr     = *(const float4*)&g_dst[kn2 + kc];
            }
        }

        // ---- MMAs on stage cur ----
        {
            const uint32_t* Wc = whs + cur * WHS_STAGE;
            const uint32_t* Pc = ps  + cur * PS_STAGE;
            #pragma unroll
            for (int kk = 0; kk < 4; kk++) {
                int kr = kk * 8 + (lane & 3);
                int cb = wn * 32 + (lane >> 2);
                uint32_t b[4][2];
                #pragma unroll
                for (int na = 0; na < 4; na++) {
                    b[na][0] = Wc[kr * WHS_STRIDE       + cb + na * 8];
                    b[na][1] = Wc[(kr + 4) * WHS_STRIDE + cb + na * 8];
                }
                #pragma unroll
                for (int ma = 0; ma < 2; ma++) {
                    int ar = wm * 32 + ma * 16 + (lane >> 2);
                    int ac = kk * 8 + (lane & 3);
                    uint32_t a0 = Pc[ar * PS_STRIDE + ac];
                    uint32_t a1 = Pc[(ar + 8) * PS_STRIDE + ac];
                    uint32_t a2 = Pc[ar * PS_STRIDE + ac + 4];
                    uint32_t a3 = Pc[(ar + 8) * PS_STRIDE + ac + 4];
                    #pragma unroll
                    for (int na = 0; na < 4; na++)
                        mma_tf32(acc[ma][na], a0, a1, a2, a3, b[na][0], b[na][1]);
                }
            }
        }
    }

    // ---- epilogue: normalize by rowsum, ELU, store ----
    #pragma unroll
    for (int ma = 0; ma < 2; ma++) {
        int rb = wm * 32 + ma * 16 + (lane >> 2);
        #pragma unroll
        for (int na = 0; na < 4; na++) {
            int c0 = J0 + wn * 32 + na * 8 + (lane & 3) * 2;
            #pragma unroll
            for (int q = 0; q < 4; q++) {
                int r = rb + ((q >= 2) ? 8 : 0);
                int c = c0 + (q & 1);
                float v = acc[ma][na][q] * linv_s[r];
                v = (v > 0.f) ? v : expm1f(v);
                out[(size_t)(I0 + r) * DOUT + c] = v;
            }
        }
    }
}

// ---------------- launch ------------------------------------------------------
extern "C" void kernel_launch(void* const* d_in, const int* in_sizes, int n_in,
                              void* d_out, int out_size) {
    const float* X   = (const float*)d_in[0];   // features [8192,512]
    const int*   adj = (const int*)  d_in[1];   // adj      [8192,8192]
    const float* W   = (const float*)d_in[2];   // W        [512,256]
    const float* a   = (const float*)d_in[3];   // a        [512,1]
    float* out = (float*)d_out;                 // [8192,256]

    static bool attr_done = false;
    if (!attr_done) {
        cudaFuncSetAttribute(k4_attn, cudaFuncAttributeMaxDynamicSharedMemorySize,
                             SMEM_BYTES);
        attr_done = true;
    }

    k1_gemm    <<<dim3(N_NODES / 64, DOUT / 64), 256>>>(X, W);
    k2_srcdst  <<<N_NODES / 8, 256>>>(a);
    k3_rowstats<<<N_NODES, 256>>>(adj);
    k4_attn    <<<dim3(N_NODES / 64, 2), 256, SMEM_BYTES>>>(adj, out);
}